// round 3
// baseline (speedup 1.0000x reference)
#include <cuda_runtime.h>
#include <math.h>

// CommNetWork: B=256, N=64, D_IN=128, H0=256, H1=256, H2=64
// One CTA per batch (64 agent rows), fully fused, activations live in SMEM.
//
// Key algebraic factorization: comm c[r] = (S - h[r])/N with S = column sums,
// so gi[r][g] = (t[g] - (h @ W_ih^T)[r][g])/N + b_ih[g], t[g] = S . W_ih[g].
// t is accumulated for free from the W_ih tiles already staged for the GEMMs.

#define LDA 68   // padded stride (floats) for K-transposed tiles (bank-conflict pad)

struct SmemLayout {
    float A [256][LDA];   // activation buffer 1, K-transposed: A[k][row]
    float A2[256][LDA];   // activation buffer 2
    float W0[64][LDA];    // weight tile 0 (K-transposed: W0[k][col])
    float W1[64][LDA];    // weight tile 1
    float S [256];        // per-batch column sums of h
    float t [768];        // t[g] = S . W_ih[g], accumulated during P5
};

__device__ __forceinline__ float sigmoidf_(float x) { return 1.0f / (1.0f + expf(-x)); }

// Stage a 64-col x 64-k weight tile, transposed: Wt[kk][c] = W[(colBase+c)*ldk + k0+kk]
// Global reads are coalesced (consecutive tid -> consecutive kk).
__device__ __forceinline__ void load_wtile(float (&Wt)[64][LDA],
                                           const float* __restrict__ W,
                                           int ldk, int colBase, int k0, int tid) {
#pragma unroll
    for (int it = 0; it < 16; ++it) {
        int idx = tid + it * 256;       // 0..4095
        int c  = idx >> 6;
        int kk = idx & 63;
        Wt[kk][c] = __ldg(&W[(size_t)(colBase + c) * ldk + (k0 + kk)]);
    }
}

// Accumulate t[gbase + c] += sum_kk S[k0+kk] * Wt[kk][c] for the staged W_ih tile.
// 256 threads: 4 partial-reducers per column, smem atomics (4-way contention).
__device__ __forceinline__ void accum_t(float* __restrict__ t, const float* __restrict__ S,
                                        const float (&Wt)[64][LDA],
                                        int gbase, int k0, int tid) {
    int c = tid & 63;
    int q = tid >> 6;           // 0..3
    float sum = 0.0f;
#pragma unroll
    for (int u = 0; u < 16; ++u) {
        int kk = q * 16 + u;
        sum = fmaf(S[k0 + kk], Wt[kk][c], sum);
    }
    atomicAdd(&t[gbase + c], sum);
}

// acc[i][j] += sum_k A[k0+k][r0+i] * Wt[k][c0+j]
__device__ __forceinline__ void mm1(const float (&A)[256][LDA], const float (&Wt)[64][LDA],
                                    int k0, int r0, int c0, float (&acc)[4][4]) {
#pragma unroll 16
    for (int k = 0; k < 64; ++k) {
        float4 av = *(const float4*)&A[k0 + k][r0];
        float4 bv = *(const float4*)&Wt[k][c0];
        float a[4] = {av.x, av.y, av.z, av.w};
        float b[4] = {bv.x, bv.y, bv.z, bv.w};
#pragma unroll
        for (int i = 0; i < 4; ++i)
#pragma unroll
            for (int j = 0; j < 4; ++j)
                acc[i][j] = fmaf(a[i], b[j], acc[i][j]);
    }
}

// Dual-accumulator sweep: one A-fragment feeds two weight tiles (32 FMA / 3 LDS.128)
__device__ __forceinline__ void mm2(const float (&A)[256][LDA],
                                    const float (&Wa)[64][LDA], const float (&Wb)[64][LDA],
                                    int k0, int r0, int c0,
                                    float (&accA)[4][4], float (&accB)[4][4]) {
#pragma unroll 8
    for (int k = 0; k < 64; ++k) {
        float4 av = *(const float4*)&A[k0 + k][r0];
        float4 b0 = *(const float4*)&Wa[k][c0];
        float4 b1 = *(const float4*)&Wb[k][c0];
        float a[4] = {av.x, av.y, av.z, av.w};
        float p[4] = {b0.x, b0.y, b0.z, b0.w};
        float q[4] = {b1.x, b1.y, b1.z, b1.w};
#pragma unroll
        for (int i = 0; i < 4; ++i)
#pragma unroll
            for (int j = 0; j < 4; ++j) {
                accA[i][j] = fmaf(a[i], p[j], accA[i][j]);
                accB[i][j] = fmaf(a[i], q[j], accB[i][j]);
            }
    }
}

__global__ void __launch_bounds__(256, 1)
commnet_kernel(const float* __restrict__ obs,
               const float* __restrict__ W_enc, const float* __restrict__ b_enc,
               const float* __restrict__ W_obs, const float* __restrict__ b_obs,
               const float* __restrict__ W_ih,  const float* __restrict__ b_ih,
               const float* __restrict__ W_hh,  const float* __restrict__ b_hh,
               const float* __restrict__ W_val, const float* __restrict__ b_val,
               const float* __restrict__ W_dec, const float* __restrict__ b_dec,
               float* __restrict__ out)
{
    extern __shared__ float smem_raw[];
    SmemLayout& s = *reinterpret_cast<SmemLayout*>(smem_raw);

    const int tid = threadIdx.x;
    const int bid = blockIdx.x;
    const int tr = tid >> 4, tc = tid & 15;
    const int r0 = tr * 4,  c0 = tc * 4;

    // ---- P1: load obs tile [64 rows x 128] K-transposed into A ----
    const float* obs_b = obs + (size_t)bid * 64 * 128;
    for (int idx = tid; idx < 64 * 128; idx += 256) {
        int r = idx >> 7, k = idx & 127;
        s.A[k][r] = obs_b[idx];
    }
    __syncthreads();

    // ---- P2: x = relu(obs @ W_enc^T + b_enc) -> A2 ----
    for (int ct = 0; ct < 4; ++ct) {
        float acc[4][4] = {};
        for (int k0 = 0; k0 < 128; k0 += 64) {
            load_wtile(s.W0, W_enc, 128, ct * 64, k0, tid);
            __syncthreads();
            mm1(s.A, s.W0, k0, r0, c0, acc);
            __syncthreads();
        }
#pragma unroll
        for (int j = 0; j < 4; ++j) {
            int col = ct * 64 + c0 + j;
            float bb = __ldg(&b_enc[col]);
#pragma unroll
            for (int i = 0; i < 4; ++i)
                s.A2[col][r0 + i] = fmaxf(acc[i][j] + bb, 0.0f);
        }
    }
    __syncthreads();

    // ---- P3: h = x @ W_obs^T + b_obs -> A ----
    for (int ct = 0; ct < 4; ++ct) {
        float acc[4][4] = {};
        for (int k0 = 0; k0 < 256; k0 += 64) {
            load_wtile(s.W0, W_obs, 256, ct * 64, k0, tid);
            __syncthreads();
            mm1(s.A2, s.W0, k0, r0, c0, acc);
            __syncthreads();
        }
#pragma unroll
        for (int j = 0; j < 4; ++j) {
            int col = ct * 64 + c0 + j;
            float bb = __ldg(&b_obs[col]);
#pragma unroll
            for (int i = 0; i < 4; ++i)
                s.A[col][r0 + i] = acc[i][j] + bb;
        }
    }
    __syncthreads();

    // ---- P4: S[f] = sum over rows of h; zero t ----
    {
        float sum = 0.0f;
#pragma unroll 8
        for (int r = 0; r < 64; ++r) sum += s.A[tid][r];
        s.S[tid] = sum;
        s.t[tid] = 0.0f;
        s.t[tid + 256] = 0.0f;
        s.t[tid + 512] = 0.0f;
    }
    __syncthreads();

    const float invN = 1.0f / 64.0f;

    // ---- P5a: r gate -> A2   (gi_r = (t - h.W_ih_r^T)/N + b_ih ; gh_r = h.W_hh_r^T + b_hh)
    for (int ct = 0; ct < 4; ++ct) {
        float aP[4][4] = {}, aQ[4][4] = {};
        for (int k0 = 0; k0 < 256; k0 += 64) {
            load_wtile(s.W0, W_ih, 256, ct * 64, k0, tid);
            load_wtile(s.W1, W_hh, 256, ct * 64, k0, tid);
            __syncthreads();
            accum_t(s.t, s.S, s.W0, ct * 64, k0, tid);
            mm2(s.A, s.W0, s.W1, k0, r0, c0, aP, aQ);
            __syncthreads();
        }
#pragma unroll
        for (int j = 0; j < 4; ++j) {
            int col = ct * 64 + c0 + j;
            float bi = __ldg(&b_ih[col]);
            float bh = __ldg(&b_hh[col]);
            float tg = s.t[col];
#pragma unroll
            for (int i = 0; i < 4; ++i) {
                float gi = (tg - aP[i][j]) * invN + bi;
                float gh = aQ[i][j] + bh;
                s.A2[col][r0 + i] = sigmoidf_(gi + gh);
            }
        }
    }
    __syncthreads();

    // ---- P5b: z, n, h_new -> A2 (reads own r element, overwrites in place) ----
    for (int ct = 0; ct < 4; ++ct) {
        float aPz[4][4] = {}, aQz[4][4] = {};
        for (int k0 = 0; k0 < 256; k0 += 64) {
            load_wtile(s.W0, W_ih, 256, 256 + ct * 64, k0, tid);
            load_wtile(s.W1, W_hh, 256, 256 + ct * 64, k0, tid);
            __syncthreads();
            accum_t(s.t, s.S, s.W0, 256 + ct * 64, k0, tid);
            mm2(s.A, s.W0, s.W1, k0, r0, c0, aPz, aQz);
            __syncthreads();
        }
        float aPn[4][4] = {}, aQn[4][4] = {};
        for (int k0 = 0; k0 < 256; k0 += 64) {
            load_wtile(s.W0, W_ih, 256, 512 + ct * 64, k0, tid);
            load_wtile(s.W1, W_hh, 256, 512 + ct * 64, k0, tid);
            __syncthreads();
            accum_t(s.t, s.S, s.W0, 512 + ct * 64, k0, tid);
            mm2(s.A, s.W0, s.W1, k0, r0, c0, aPn, aQn);
            __syncthreads();
        }
#pragma unroll
        for (int j = 0; j < 4; ++j) {
            int col = ct * 64 + c0 + j;
            int gz = 256 + col, gn = 512 + col;
            float biz = __ldg(&b_ih[gz]), bhz = __ldg(&b_hh[gz]);
            float bin_ = __ldg(&b_ih[gn]), bhn = __ldg(&b_hh[gn]);
            float tz = s.t[gz], tn = s.t[gn];
#pragma unroll
            for (int i = 0; i < 4; ++i) {
                float z  = sigmoidf_((tz - aPz[i][j]) * invN + biz + aQz[i][j] + bhz);
                float rr = s.A2[col][r0 + i];
                float n  = tanhf((tn - aPn[i][j]) * invN + bin_ + rr * (aQn[i][j] + bhn));
                float hold = s.A[col][r0 + i];
                s.A2[col][r0 + i] = (1.0f - z) * n + z * hold;
            }
        }
    }
    __syncthreads();

    // ---- P6: v = h_new @ W_val^T + b_val -> A ----
    for (int ct = 0; ct < 2; ++ct) {
        float aP[4][4] = {}, aQ[4][4] = {};
        int cbP = ct * 128, cbQ = ct * 128 + 64;
        for (int k0 = 0; k0 < 256; k0 += 64) {
            load_wtile(s.W0, W_val, 256, cbP, k0, tid);
            load_wtile(s.W1, W_val, 256, cbQ, k0, tid);
            __syncthreads();
            mm2(s.A2, s.W0, s.W1, k0, r0, c0, aP, aQ);
            __syncthreads();
        }
#pragma unroll
        for (int j = 0; j < 4; ++j) {
            int colP = cbP + c0 + j;
            int colQ = cbQ + c0 + j;
            float bP = __ldg(&b_val[colP]);
            float bQ = __ldg(&b_val[colQ]);
#pragma unroll
            for (int i = 0; i < 4; ++i) {
                s.A[colP][r0 + i] = aP[i][j] + bP;
                s.A[colQ][r0 + i] = aQ[i][j] + bQ;
            }
        }
    }
    __syncthreads();

    // ---- P7: out = v @ W_dec^T + b_dec -> global ----
    {
        float acc[4][4] = {};
        for (int k0 = 0; k0 < 256; k0 += 64) {
            load_wtile(s.W0, W_dec, 256, 0, k0, tid);
            __syncthreads();
            mm1(s.A, s.W0, k0, r0, c0, acc);
            __syncthreads();
        }
        float b0 = __ldg(&b_dec[c0 + 0]);
        float b1 = __ldg(&b_dec[c0 + 1]);
        float b2 = __ldg(&b_dec[c0 + 2]);
        float b3 = __ldg(&b_dec[c0 + 3]);
        float* out_b = out + (size_t)bid * 64 * 64;
#pragma unroll
        for (int i = 0; i < 4; ++i) {
            float4 o;
            o.x = acc[i][0] + b0;
            o.y = acc[i][1] + b1;
            o.z = acc[i][2] + b2;
            o.w = acc[i][3] + b3;
            *(float4*)&out_b[(r0 + i) * 64 + c0] = o;
        }
    }
}

extern "C" void kernel_launch(void* const* d_in, const int* in_sizes, int n_in,
                              void* d_out, int out_size)
{
    const float* obs   = (const float*)d_in[0];
    const float* W_enc = (const float*)d_in[1];
    const float* b_enc = (const float*)d_in[2];
    const float* W_obs = (const float*)d_in[3];
    const float* b_obs = (const float*)d_in[4];
    const float* W_ih  = (const float*)d_in[5];
    const float* b_ih  = (const float*)d_in[6];
    const float* W_hh  = (const float*)d_in[7];
    const float* b_hh  = (const float*)d_in[8];
    const float* W_val = (const float*)d_in[9];
    const float* b_val = (const float*)d_in[10];
    const float* W_dec = (const float*)d_in[11];
    const float* b_dec = (const float*)d_in[12];
    float* out = (float*)d_out;

    (void)in_sizes; (void)n_in; (void)out_size;

    cudaFuncSetAttribute(commnet_kernel,
                         cudaFuncAttributeMaxDynamicSharedMemorySize,
                         (int)sizeof(SmemLayout));

    commnet_kernel<<<256, 256, sizeof(SmemLayout)>>>(
        obs, W_enc, b_enc, W_obs, b_obs, W_ih, b_ih, W_hh, b_hh,
        W_val, b_val, W_dec, b_dec, out);
}

// round 6
// speedup vs baseline: 1.2644x; 1.2644x over previous
#include <cuda_runtime.h>
#include <cuda_bf16.h>
#include <stdint.h>
#include <math.h>

// CommNetWork fused, split-bf16 tensor cores (mma.sync.m16n8k16.bf16, fp32 acc).
// B=256, N=64 agents, D_IN=128, H0=256, H1=256, H2=64. One CTA per batch.
// Precision: x*w ~= xh*wh + xh*wl + xl*wh (hi/lo bf16 split, fp32 accumulate).
// Comm factorization: c=(S-h)/64; W_ih pre-scaled by -1/64 so gi and gh share
// one accumulator; the S-term t[col] is accumulated from staged chunks.

#define ROWS    64
#define LDA_ACT 264   // bf16 elems per activation row (256+8 pad)
#define LDW     40    // bf16 elems per weight-chunk row (32+8 pad)
#define KCH     32    // k per staged chunk (double buffered)

#define OFF_ENC 0
#define OFF_OBS 32768
#define OFF_IH  98304
#define OFF_HH  294912
#define OFF_VAL 491520
#define OFF_DEC 557056
#define W_TOTAL 573440

__device__ __align__(16) __nv_bfloat16 g_whi[W_TOTAL];
__device__ __align__(16) __nv_bfloat16 g_wlo[W_TOTAL];

struct Smem {
    __nv_bfloat16 a1h[ROWS * LDA_ACT];
    __nv_bfloat16 a1l[ROWS * LDA_ACT];
    __nv_bfloat16 a2h[ROWS * LDA_ACT];
    __nv_bfloat16 a2l[ROWS * LDA_ACT];
    __nv_bfloat16 wh[2][256 * LDW];
    __nv_bfloat16 wl[2][256 * LDW];
    float S[256];
    float t[256];
};  // 219136 bytes

// ------------------------- weight conversion pre-pass -------------------
__global__ void conv_weights(const float* __restrict__ enc, const float* __restrict__ obsw,
                             const float* __restrict__ ih,  const float* __restrict__ hh,
                             const float* __restrict__ val, const float* __restrict__ dec)
{
    int i = blockIdx.x * blockDim.x + threadIdx.x;
    if (i >= W_TOTAL) return;
    const float* src;
    int off;
    float scale = 1.0f;
    if (i < OFF_OBS)      { src = enc;  off = i; }
    else if (i < OFF_IH)  { src = obsw; off = i - OFF_OBS; }
    else if (i < OFF_HH)  { src = ih;   off = i - OFF_IH; scale = -0.015625f; }
    else if (i < OFF_VAL) { src = hh;   off = i - OFF_HH; }
    else if (i < OFF_DEC) { src = val;  off = i - OFF_VAL; }
    else                  { src = dec;  off = i - OFF_DEC; }
    float v = src[off] * scale;
    __nv_bfloat16 h = __float2bfloat16(v);
    g_whi[i] = h;
    g_wlo[i] = __float2bfloat16(v - __bfloat162float(h));
}

// ------------------------- device helpers --------------------------------
__device__ __forceinline__ float sigm(float x) { return 1.0f / (1.0f + __expf(-x)); }

__device__ __forceinline__ void cp16(void* dst, const void* src) {
    uint32_t d = (uint32_t)__cvta_generic_to_shared(dst);
    asm volatile("cp.async.cg.shared.global [%0], [%1], 16;\n" :: "r"(d), "l"(src));
}
__device__ __forceinline__ void cp_commit() { asm volatile("cp.async.commit_group;\n" ::); }
__device__ __forceinline__ void cp_wait1()  { asm volatile("cp.async.wait_group 1;\n" ::); }
__device__ __forceinline__ void cp_wait0()  { asm volatile("cp.async.wait_group 0;\n" ::); }

__device__ __forceinline__ void mma_bf16(float* d,
                                         uint32_t a0, uint32_t a1, uint32_t a2, uint32_t a3,
                                         uint32_t b0, uint32_t b1)
{
    asm volatile("mma.sync.aligned.m16n8k16.row.col.f32.bf16.bf16.f32 "
                 "{%0,%1,%2,%3}, {%4,%5,%6,%7}, {%8,%9}, {%0,%1,%2,%3};\n"
                 : "+f"(d[0]), "+f"(d[1]), "+f"(d[2]), "+f"(d[3])
                 : "r"(a0), "r"(a1), "r"(a2), "r"(a3), "r"(b0), "r"(b1));
}

__device__ __forceinline__ void stage(Smem& s, int buf,
                                      const __nv_bfloat16* __restrict__ ghi,
                                      const __nv_bfloat16* __restrict__ glo,
                                      int col0, int Ksrc, int k0, int nrows, int tid)
{
    int total = nrows * 4;
    for (int idx = tid; idx < total; idx += 256) {
        int r = idx >> 2;
        int seg = idx & 3;
        size_t so = (size_t)(col0 + r) * Ksrc + k0 + seg * 8;
        cp16(&s.wh[buf][r * LDW + seg * 8], ghi + so);
        cp16(&s.wl[buf][r * LDW + seg * 8], glo + so);
    }
    cp_commit();
}

// one 32-k chunk: acc += Ahi*Whi + Ahi*Wlo + Alo*Whi
template<int NT>
__device__ __forceinline__ void mma_chunk(const __nv_bfloat16* __restrict__ ah,
                                          const __nv_bfloat16* __restrict__ al,
                                          const __nv_bfloat16* __restrict__ wh,
                                          const __nv_bfloat16* __restrict__ wl,
                                          int kbase, int n0, int g, int t4, float* acc)
{
#pragma unroll
    for (int ks = 0; ks < 2; ++ks) {
        int klA = kbase + ks * 16 + 2 * t4;
        int klW = ks * 16 + 2 * t4;
        uint32_t bh0[NT], bh1[NT], bl0[NT], bl1[NT];
#pragma unroll
        for (int nt = 0; nt < NT; ++nt) {
            int wrow = (n0 + nt * 8 + g) * LDW + klW;
            bh0[nt] = *(const uint32_t*)&wh[wrow];
            bh1[nt] = *(const uint32_t*)&wh[wrow + 8];
            bl0[nt] = *(const uint32_t*)&wl[wrow];
            bl1[nt] = *(const uint32_t*)&wl[wrow + 8];
        }
#pragma unroll
        for (int mt = 0; mt < 4; ++mt) {
            int ab = (mt * 16 + g) * LDA_ACT + klA;
            uint32_t A0 = *(const uint32_t*)&ah[ab];
            uint32_t A1 = *(const uint32_t*)&ah[ab + 8 * LDA_ACT];
            uint32_t A2 = *(const uint32_t*)&ah[ab + 8];
            uint32_t A3 = *(const uint32_t*)&ah[ab + 8 * LDA_ACT + 8];
            uint32_t L0 = *(const uint32_t*)&al[ab];
            uint32_t L1 = *(const uint32_t*)&al[ab + 8 * LDA_ACT];
            uint32_t L2 = *(const uint32_t*)&al[ab + 8];
            uint32_t L3 = *(const uint32_t*)&al[ab + 8 * LDA_ACT + 8];
#pragma unroll
            for (int nt = 0; nt < NT; ++nt) {
                float* d = acc + (mt * NT + nt) * 4;
                mma_bf16(d, A0, A1, A2, A3, bh0[nt], bh1[nt]);
                mma_bf16(d, A0, A1, A2, A3, bl0[nt], bl1[nt]);
                mma_bf16(d, L0, L1, L2, L3, bh0[nt], bh1[nt]);
            }
        }
    }
}

template<int NT, bool TACC>
__device__ __forceinline__ void gemm_pass(Smem& s,
                                          const __nv_bfloat16* __restrict__ ah,
                                          const __nv_bfloat16* __restrict__ al,
                                          const __nv_bfloat16* __restrict__ ghi,
                                          const __nv_bfloat16* __restrict__ glo,
                                          int col0, int Ksrc, int Kdim, int nrows,
                                          int n0, int g, int t4, int tid, float* acc)
{
    const int nch = Kdim / KCH;
    stage(s, 0, ghi, glo, col0, Ksrc, 0, nrows, tid);
    for (int c = 0; c < nch; ++c) {
        int cur = c & 1;
        bool more = (c + 1 < nch);
        if (more) {
            stage(s, 1 - cur, ghi, glo, col0, Ksrc, (c + 1) * KCH, nrows, tid);
            cp_wait1();
        } else {
            cp_wait0();
        }
        __syncthreads();
        if (TACC) {
            float sum = 0.0f;
            const __nv_bfloat16* w1 = &s.wh[cur][tid * LDW];
            const __nv_bfloat16* w2 = &s.wl[cur][tid * LDW];
#pragma unroll
            for (int kk = 0; kk < KCH; ++kk) {
                sum += s.S[c * KCH + kk] *
                       (__bfloat162float(w1[kk]) + __bfloat162float(w2[kk]));
            }
            s.t[tid] += sum;
        }
        mma_chunk<NT>(ah, al, s.wh[cur], s.wl[cur], c * KCH, n0, g, t4, acc);
        __syncthreads();
    }
}

__device__ __forceinline__ void store_pair(__nv_bfloat16* hi, __nv_bfloat16* lo,
                                           int row, int col, float v0, float v1)
{
    __nv_bfloat16 h0 = __float2bfloat16(v0);
    __nv_bfloat16 h1 = __float2bfloat16(v1);
    __nv_bfloat162 hp;
    hp.x = h0;
    hp.y = h1;
    __nv_bfloat162 lp;
    lp.x = __float2bfloat16(v0 - __bfloat162float(h0));
    lp.y = __float2bfloat16(v1 - __bfloat162float(h1));
    *reinterpret_cast<__nv_bfloat162*>(&hi[row * LDA_ACT + col]) = hp;
    *reinterpret_cast<__nv_bfloat162*>(&lo[row * LDA_ACT + col]) = lp;
}

__device__ __forceinline__ float2 load_pair(const __nv_bfloat16* hi, const __nv_bfloat16* lo,
                                            int row, int col)
{
    __nv_bfloat162 hp = *reinterpret_cast<const __nv_bfloat162*>(&hi[row * LDA_ACT + col]);
    __nv_bfloat162 lp = *reinterpret_cast<const __nv_bfloat162*>(&lo[row * LDA_ACT + col]);
    float2 r;
    r.x = __bfloat162float(hp.x) + __bfloat162float(lp.x);
    r.y = __bfloat162float(hp.y) + __bfloat162float(lp.y);
    return r;
}

__device__ __forceinline__ void zero64(float* a)
{
#pragma unroll
    for (int i = 0; i < 64; ++i) { a[i] = 0.0f; }
}

// ------------------------- main fused kernel -----------------------------
__global__ void __launch_bounds__(256, 1)
commnet_mma_kernel(const float* __restrict__ obs,
                   const float* __restrict__ b_enc, const float* __restrict__ b_obs,
                   const float* __restrict__ b_ih,  const float* __restrict__ b_hh,
                   const float* __restrict__ b_val, const float* __restrict__ b_dec,
                   float* __restrict__ out)
{
    extern __shared__ char smem_raw[];
    Smem& s = *reinterpret_cast<Smem*>(smem_raw);

    const int tid  = threadIdx.x;
    const int bid  = blockIdx.x;
    const int wid  = tid >> 5;
    const int lane = tid & 31;
    const int g    = lane >> 2;
    const int t4   = lane & 3;
    const int n0g  = wid * 32;

    float acc[64];

    // ---- P1: load obs [64 x 128] -> a1 hi/lo ----
    {
        const float* ob = obs + (size_t)bid * ROWS * 128;
        for (int idx = tid; idx < ROWS * 128; idx += 256) {
            int r = idx >> 7;
            int k = idx & 127;
            float v = ob[idx];
            __nv_bfloat16 h = __float2bfloat16(v);
            s.a1h[r * LDA_ACT + k] = h;
            s.a1l[r * LDA_ACT + k] = __float2bfloat16(v - __bfloat162float(h));
        }
    }
    __syncthreads();

    // ---- P2: x = relu(obs @ W_enc^T + b_enc) -> a2 ----
    zero64(acc);
    gemm_pass<4, false>(s, s.a1h, s.a1l, g_whi + OFF_ENC, g_wlo + OFF_ENC,
                        0, 128, 128, 256, n0g, g, t4, tid, acc);
    for (int mt = 0; mt < 4; ++mt) {
        for (int nt = 0; nt < 4; ++nt) {
            int col = n0g + nt * 8 + 2 * t4;
            int r0 = mt * 16 + g;
            const float* d = acc + (mt * 4 + nt) * 4;
            float b0 = __ldg(&b_enc[col]);
            float b1 = __ldg(&b_enc[col + 1]);
            store_pair(s.a2h, s.a2l, r0, col, fmaxf(d[0] + b0, 0.0f), fmaxf(d[1] + b1, 0.0f));
            store_pair(s.a2h, s.a2l, r0 + 8, col, fmaxf(d[2] + b0, 0.0f), fmaxf(d[3] + b1, 0.0f));
        }
    }

    // ---- P3: h = x @ W_obs^T + b_obs -> a1 ----
    zero64(acc);
    gemm_pass<4, false>(s, s.a2h, s.a2l, g_whi + OFF_OBS, g_wlo + OFF_OBS,
                        0, 256, 256, 256, n0g, g, t4, tid, acc);
    for (int mt = 0; mt < 4; ++mt) {
        for (int nt = 0; nt < 4; ++nt) {
            int col = n0g + nt * 8 + 2 * t4;
            int r0 = mt * 16 + g;
            const float* d = acc + (mt * 4 + nt) * 4;
            float b0 = __ldg(&b_obs[col]);
            float b1 = __ldg(&b_obs[col + 1]);
            store_pair(s.a1h, s.a1l, r0, col, d[0] + b0, d[1] + b1);
            store_pair(s.a1h, s.a1l, r0 + 8, col, d[2] + b0, d[3] + b1);
        }
    }
    __syncthreads();

    // ---- P4: S = column sums of h ----
    {
        float sum = 0.0f;
#pragma unroll 8
        for (int r = 0; r < ROWS; ++r) {
            sum += __bfloat162float(s.a1h[r * LDA_ACT + tid]) +
                   __bfloat162float(s.a1l[r * LDA_ACT + tid]);
        }
        s.S[tid] = sum;
    }
    __syncthreads();

    // ======== P5 GRU. Gate fragments round-trip through a2 (own-thread). ====

    // r gate
    zero64(acc);
    gemm_pass<4, false>(s, s.a1h, s.a1l, g_whi + OFF_HH, g_wlo + OFF_HH,
                        0, 256, 256, 256, n0g, g, t4, tid, acc);
    s.t[tid] = 0.0f;
    gemm_pass<4, true>(s, s.a1h, s.a1l, g_whi + OFF_IH, g_wlo + OFF_IH,
                       0, 256, 256, 256, n0g, g, t4, tid, acc);
    for (int mt = 0; mt < 4; ++mt) {
        for (int nt = 0; nt < 4; ++nt) {
            int col = n0g + nt * 8 + 2 * t4;
            int r0 = mt * 16 + g;
            float* d = acc + (mt * 4 + nt) * 4;
            float c0 = -s.t[col] + __ldg(&b_ih[col]) + __ldg(&b_hh[col]);
            float c1 = -s.t[col + 1] + __ldg(&b_ih[col + 1]) + __ldg(&b_hh[col + 1]);
            store_pair(s.a2h, s.a2l, r0, col, sigm(d[0] + c0), sigm(d[1] + c1));
            store_pair(s.a2h, s.a2l, r0 + 8, col, sigm(d[2] + c0), sigm(d[3] + c1));
        }
    }

    // n gate: acc = h.Whh_n; acc = r*(acc+b_hh_n); acc += h.Wih'_n; n = tanh(acc - t + b_ih_n)
    zero64(acc);
    gemm_pass<4, false>(s, s.a1h, s.a1l, g_whi + OFF_HH, g_wlo + OFF_HH,
                        512, 256, 256, 256, n0g, g, t4, tid, acc);
    for (int mt = 0; mt < 4; ++mt) {
        for (int nt = 0; nt < 4; ++nt) {
            int col = n0g + nt * 8 + 2 * t4;
            int r0 = mt * 16 + g;
            float* d = acc + (mt * 4 + nt) * 4;
            float b0 = __ldg(&b_hh[512 + col]);
            float b1 = __ldg(&b_hh[512 + col + 1]);
            float2 ra = load_pair(s.a2h, s.a2l, r0, col);
            float2 rb = load_pair(s.a2h, s.a2l, r0 + 8, col);
            d[0] = ra.x * (d[0] + b0);
            d[1] = ra.y * (d[1] + b1);
            d[2] = rb.x * (d[2] + b0);
            d[3] = rb.y * (d[3] + b1);
        }
    }
    s.t[tid] = 0.0f;
    gemm_pass<4, true>(s, s.a1h, s.a1l, g_whi + OFF_IH, g_wlo + OFF_IH,
                       512, 256, 256, 256, n0g, g, t4, tid, acc);
    for (int mt = 0; mt < 4; ++mt) {
        for (int nt = 0; nt < 4; ++nt) {
            int col = n0g + nt * 8 + 2 * t4;
            int r0 = mt * 16 + g;
            float* d = acc + (mt * 4 + nt) * 4;
            float c0 = -s.t[col] + __ldg(&b_ih[512 + col]);
            float c1 = -s.t[col + 1] + __ldg(&b_ih[512 + col + 1]);
            store_pair(s.a2h, s.a2l, r0, col, tanhf(d[0] + c0), tanhf(d[1] + c1));
            store_pair(s.a2h, s.a2l, r0 + 8, col, tanhf(d[2] + c0), tanhf(d[3] + c1));
        }
    }

    // z gate + blend: h_new = (1-z)*n + z*h_old -> a2
    zero64(acc);
    gemm_pass<4, false>(s, s.a1h, s.a1l, g_whi + OFF_HH, g_wlo + OFF_HH,
                        256, 256, 256, 256, n0g, g, t4, tid, acc);
    s.t[tid] = 0.0f;
    gemm_pass<4, true>(s, s.a1h, s.a1l, g_whi + OFF_IH, g_wlo + OFF_IH,
                       256, 256, 256, 256, n0g, g, t4, tid, acc);
    for (int mt = 0; mt < 4; ++mt) {
        for (int nt = 0; nt < 4; ++nt) {
            int col = n0g + nt * 8 + 2 * t4;
            int r0 = mt * 16 + g;
            float* d = acc + (mt * 4 + nt) * 4;
            float c0 = -s.t[col] + __ldg(&b_ih[256 + col]) + __ldg(&b_hh[256 + col]);
            float c1 = -s.t[col + 1] + __ldg(&b_ih[256 + col + 1]) + __ldg(&b_hh[256 + col + 1]);
            float z0 = sigm(d[0] + c0);
            float z1 = sigm(d[1] + c1);
            float z2 = sigm(d[2] + c0);
            float z3 = sigm(d[3] + c1);
            float2 na = load_pair(s.a2h, s.a2l, r0, col);
            float2 nb = load_pair(s.a2h, s.a2l, r0 + 8, col);
            float2 ha = load_pair(s.a1h, s.a1l, r0, col);
            float2 hb = load_pair(s.a1h, s.a1l, r0 + 8, col);
            store_pair(s.a2h, s.a2l, r0, col,
                       (1.0f - z0) * na.x + z0 * ha.x,
                       (1.0f - z1) * na.y + z1 * ha.y);
            store_pair(s.a2h, s.a2l, r0 + 8, col,
                       (1.0f - z2) * nb.x + z2 * hb.x,
                       (1.0f - z3) * nb.y + z3 * hb.y);
        }
    }

    // ---- P6: v = h_new @ W_val^T + b_val -> a1 ----
    zero64(acc);
    gemm_pass<4, false>(s, s.a2h, s.a2l, g_whi + OFF_VAL, g_wlo + OFF_VAL,
                        0, 256, 256, 256, n0g, g, t4, tid, acc);
    for (int mt = 0; mt < 4; ++mt) {
        for (int nt = 0; nt < 4; ++nt) {
            int col = n0g + nt * 8 + 2 * t4;
            int r0 = mt * 16 + g;
            const float* d = acc + (mt * 4 + nt) * 4;
            float b0 = __ldg(&b_val[col]);
            float b1 = __ldg(&b_val[col + 1]);
            store_pair(s.a1h, s.a1l, r0, col, d[0] + b0, d[1] + b1);
            store_pair(s.a1h, s.a1l, r0 + 8, col, d[2] + b0, d[3] + b1);
        }
    }

    // ---- P7: out = v @ W_dec^T + b_dec (64 cols, warp owns 8) ----
    {
        float ad[16];
#pragma unroll
        for (int i = 0; i < 16; ++i) { ad[i] = 0.0f; }
        int n0d = wid * 8;
        gemm_pass<1, false>(s, s.a1h, s.a1l, g_whi + OFF_DEC, g_wlo + OFF_DEC,
                            0, 256, 256, 64, n0d, g, t4, tid, ad);
        float* out_b = out + (size_t)bid * ROWS * 64;
        int col = n0d + 2 * t4;
        float b0 = __ldg(&b_dec[col]);
        float b1 = __ldg(&b_dec[col + 1]);
        for (int mt = 0; mt < 4; ++mt) {
            int r0 = mt * 16 + g;
            const float* d = ad + mt * 4;
            float2 o0 = make_float2(d[0] + b0, d[1] + b1);
            float2 o1 = make_float2(d[2] + b0, d[3] + b1);
            *reinterpret_cast<float2*>(&out_b[r0 * 64 + col]) = o0;
            *reinterpret_cast<float2*>(&out_b[(r0 + 8) * 64 + col]) = o1;
        }
    }
}

extern "C" void kernel_launch(void* const* d_in, const int* in_sizes, int n_in,
                              void* d_out, int out_size)
{
    const float* obs   = (const float*)d_in[0];
    const float* W_enc = (const float*)d_in[1];
    const float* b_enc = (const float*)d_in[2];
    const float* W_obs = (const float*)d_in[3];
    const float* b_obs = (const float*)d_in[4];
    const float* W_ih  = (const float*)d_in[5];
    const float* b_ih  = (const float*)d_in[6];
    const float* W_hh  = (const float*)d_in[7];
    const float* b_hh  = (const float*)d_in[8];
    const float* W_val = (const float*)d_in[9];
    const float* b_val = (const float*)d_in[10];
    const float* W_dec = (const float*)d_in[11];
    const float* b_dec = (const float*)d_in[12];
    float* out = (float*)d_out;
    (void)in_sizes; (void)n_in; (void)out_size;

    conv_weights<<<(W_TOTAL + 255) / 256, 256>>>(W_enc, W_obs, W_ih, W_hh, W_val, W_dec);

    cudaFuncSetAttribute(commnet_mma_kernel,
                         cudaFuncAttributeMaxDynamicSharedMemorySize, (int)sizeof(Smem));
    commnet_mma_kernel<<<256, 256, sizeof(Smem)>>>(
        obs, b_enc, b_obs, b_ih, b_hh, b_val, b_dec, out);
}

// round 7
// speedup vs baseline: 1.2679x; 1.0028x over previous
#include <cuda_runtime.h>
#include <cuda_bf16.h>
#include <stdint.h>
#include <math.h>

// CommNetWork fused, split-bf16 tensor cores (mma.sync.m16n8k16.bf16, fp32 acc).
// B=256, N=64 agents, D_IN=128, H0=256, H1=256, H2=64. One CTA per batch.
// Precision: x*w ~= xh*wh + xh*wl + xl*wh (hi/lo bf16 split, fp32 accumulate).
// Comm factorization: c=(S-h)/64; W_ih pre-scaled by -1/64 so gi and gh share
// one accumulator; the S-term t[col] is accumulated from staged chunks.

#define ROWS    64
#define LDA_ACT 264   // bf16 elems per activation row (256+8 pad)
#define LDW     40    // bf16 elems per weight-chunk row (32+8 pad)
#define KCH     32    // k per staged chunk (double buffered)

#define OFF_ENC 0
#define OFF_OBS 32768
#define OFF_IH  98304
#define OFF_HH  294912
#define OFF_VAL 491520
#define OFF_DEC 557056
#define W_TOTAL 573440

__device__ __align__(16) __nv_bfloat16 g_whi[W_TOTAL];
__device__ __align__(16) __nv_bfloat16 g_wlo[W_TOTAL];

struct Smem {
    __nv_bfloat16 a1h[ROWS * LDA_ACT];
    __nv_bfloat16 a1l[ROWS * LDA_ACT];
    __nv_bfloat16 a2h[ROWS * LDA_ACT];
    __nv_bfloat16 a2l[ROWS * LDA_ACT];
    __nv_bfloat16 wh[2][256 * LDW];
    __nv_bfloat16 wl[2][256 * LDW];
    float S[256];
    float t[256];
};  // 219136 bytes

// ------------------------- weight conversion pre-pass -------------------
__global__ void conv_weights(const float* __restrict__ enc, const float* __restrict__ obsw,
                             const float* __restrict__ ih,  const float* __restrict__ hh,
                             const float* __restrict__ val, const float* __restrict__ dec)
{
    int i = blockIdx.x * blockDim.x + threadIdx.x;
    if (i >= W_TOTAL) return;
    const float* src;
    int off;
    float scale = 1.0f;
    if (i < OFF_OBS)      { src = enc;  off = i; }
    else if (i < OFF_IH)  { src = obsw; off = i - OFF_OBS; }
    else if (i < OFF_HH)  { src = ih;   off = i - OFF_IH; scale = -0.015625f; }
    else if (i < OFF_VAL) { src = hh;   off = i - OFF_HH; }
    else if (i < OFF_DEC) { src = val;  off = i - OFF_VAL; }
    else                  { src = dec;  off = i - OFF_DEC; }
    float v = src[off] * scale;
    __nv_bfloat16 h = __float2bfloat16(v);
    g_whi[i] = h;
    g_wlo[i] = __float2bfloat16(v - __bfloat162float(h));
}

// ------------------------- device helpers --------------------------------
__device__ __forceinline__ float sigm(float x) { return 1.0f / (1.0f + __expf(-x)); }

__device__ __forceinline__ void cp16(void* dst, const void* src) {
    uint32_t d = (uint32_t)__cvta_generic_to_shared(dst);
    asm volatile("cp.async.cg.shared.global [%0], [%1], 16;\n" :: "r"(d), "l"(src));
}
__device__ __forceinline__ void cp_commit() { asm volatile("cp.async.commit_group;\n" ::); }
__device__ __forceinline__ void cp_wait1()  { asm volatile("cp.async.wait_group 1;\n" ::); }
__device__ __forceinline__ void cp_wait0()  { asm volatile("cp.async.wait_group 0;\n" ::); }

__device__ __forceinline__ void mma_bf16(float* d,
                                         uint32_t a0, uint32_t a1, uint32_t a2, uint32_t a3,
                                         uint32_t b0, uint32_t b1)
{
    asm volatile("mma.sync.aligned.m16n8k16.row.col.f32.bf16.bf16.f32 "
                 "{%0,%1,%2,%3}, {%4,%5,%6,%7}, {%8,%9}, {%0,%1,%2,%3};\n"
                 : "+f"(d[0]), "+f"(d[1]), "+f"(d[2]), "+f"(d[3])
                 : "r"(a0), "r"(a1), "r"(a2), "r"(a3), "r"(b0), "r"(b1));
}

__device__ __forceinline__ void stage(Smem& s, int buf,
                                      const __nv_bfloat16* __restrict__ ghi,
                                      const __nv_bfloat16* __restrict__ glo,
                                      int col0, int Ksrc, int k0, int nrows, int tid)
{
    int total = nrows * 4;
    for (int idx = tid; idx < total; idx += 256) {
        int r = idx >> 2;
        int seg = idx & 3;
        size_t so = (size_t)(col0 + r) * Ksrc + k0 + seg * 8;
        cp16(&s.wh[buf][r * LDW + seg * 8], ghi + so);
        cp16(&s.wl[buf][r * LDW + seg * 8], glo + so);
    }
    cp_commit();
}

// one 32-k chunk: acc += Ahi*Whi + Ahi*Wlo + Alo*Whi
template<int NT>
__device__ __forceinline__ void mma_chunk(const __nv_bfloat16* __restrict__ ah,
                                          const __nv_bfloat16* __restrict__ al,
                                          const __nv_bfloat16* __restrict__ wh,
                                          const __nv_bfloat16* __restrict__ wl,
                                          int kbase, int n0, int g, int t4, float* acc)
{
#pragma unroll
    for (int ks = 0; ks < 2; ++ks) {
        int klA = kbase + ks * 16 + 2 * t4;
        int klW = ks * 16 + 2 * t4;
        uint32_t bh0[NT], bh1[NT], bl0[NT], bl1[NT];
#pragma unroll
        for (int nt = 0; nt < NT; ++nt) {
            int wrow = (n0 + nt * 8 + g) * LDW + klW;
            bh0[nt] = *(const uint32_t*)&wh[wrow];
            bh1[nt] = *(const uint32_t*)&wh[wrow + 8];
            bl0[nt] = *(const uint32_t*)&wl[wrow];
            bl1[nt] = *(const uint32_t*)&wl[wrow + 8];
        }
#pragma unroll
        for (int mt = 0; mt < 4; ++mt) {
            int ab = (mt * 16 + g) * LDA_ACT + klA;
            uint32_t A0 = *(const uint32_t*)&ah[ab];
            uint32_t A1 = *(const uint32_t*)&ah[ab + 8 * LDA_ACT];
            uint32_t A2 = *(const uint32_t*)&ah[ab + 8];
            uint32_t A3 = *(const uint32_t*)&ah[ab + 8 * LDA_ACT + 8];
            uint32_t L0 = *(const uint32_t*)&al[ab];
            uint32_t L1 = *(const uint32_t*)&al[ab + 8 * LDA_ACT];
            uint32_t L2 = *(const uint32_t*)&al[ab + 8];
            uint32_t L3 = *(const uint32_t*)&al[ab + 8 * LDA_ACT + 8];
#pragma unroll
            for (int nt = 0; nt < NT; ++nt) {
                float* d = acc + (mt * NT + nt) * 4;
                mma_bf16(d, A0, A1, A2, A3, bh0[nt], bh1[nt]);
                mma_bf16(d, A0, A1, A2, A3, bl0[nt], bl1[nt]);
                mma_bf16(d, L0, L1, L2, L3, bh0[nt], bh1[nt]);
            }
        }
    }
}

template<int NT, bool TACC>
__device__ __forceinline__ void gemm_pass(Smem& s,
                                          const __nv_bfloat16* __restrict__ ah,
                                          const __nv_bfloat16* __restrict__ al,
                                          const __nv_bfloat16* __restrict__ ghi,
                                          const __nv_bfloat16* __restrict__ glo,
                                          int col0, int Ksrc, int Kdim, int nrows,
                                          int n0, int g, int t4, int tid, float* acc)
{
    const int nch = Kdim / KCH;
    stage(s, 0, ghi, glo, col0, Ksrc, 0, nrows, tid);
    for (int c = 0; c < nch; ++c) {
        int cur = c & 1;
        bool more = (c + 1 < nch);
        if (more) {
            stage(s, 1 - cur, ghi, glo, col0, Ksrc, (c + 1) * KCH, nrows, tid);
            cp_wait1();
        } else {
            cp_wait0();
        }
        __syncthreads();
        if (TACC) {
            float sum = 0.0f;
            const __nv_bfloat16* w1 = &s.wh[cur][tid * LDW];
            const __nv_bfloat16* w2 = &s.wl[cur][tid * LDW];
#pragma unroll
            for (int kk = 0; kk < KCH; ++kk) {
                sum += s.S[c * KCH + kk] *
                       (__bfloat162float(w1[kk]) + __bfloat162float(w2[kk]));
            }
            s.t[tid] += sum;
        }
        mma_chunk<NT>(ah, al, s.wh[cur], s.wl[cur], c * KCH, n0, g, t4, acc);
        __syncthreads();
    }
}

__device__ __forceinline__ void store_pair(__nv_bfloat16* hi, __nv_bfloat16* lo,
                                           int row, int col, float v0, float v1)
{
    __nv_bfloat16 h0 = __float2bfloat16(v0);
    __nv_bfloat16 h1 = __float2bfloat16(v1);
    __nv_bfloat162 hp;
    hp.x = h0;
    hp.y = h1;
    __nv_bfloat162 lp;
    lp.x = __float2bfloat16(v0 - __bfloat162float(h0));
    lp.y = __float2bfloat16(v1 - __bfloat162float(h1));
    *reinterpret_cast<__nv_bfloat162*>(&hi[row * LDA_ACT + col]) = hp;
    *reinterpret_cast<__nv_bfloat162*>(&lo[row * LDA_ACT + col]) = lp;
}

__device__ __forceinline__ float2 load_pair(const __nv_bfloat16* hi, const __nv_bfloat16* lo,
                                            int row, int col)
{
    __nv_bfloat162 hp = *reinterpret_cast<const __nv_bfloat162*>(&hi[row * LDA_ACT + col]);
    __nv_bfloat162 lp = *reinterpret_cast<const __nv_bfloat162*>(&lo[row * LDA_ACT + col]);
    float2 r;
    r.x = __bfloat162float(hp.x) + __bfloat162float(lp.x);
    r.y = __bfloat162float(hp.y) + __bfloat162float(lp.y);
    return r;
}

__device__ __forceinline__ void zero64(float* a)
{
#pragma unroll
    for (int i = 0; i < 64; ++i) { a[i] = 0.0f; }
}

// ------------------------- main fused kernel -----------------------------
__global__ void __launch_bounds__(256, 1)
commnet_mma_kernel(const float* __restrict__ obs,
                   const float* __restrict__ b_enc, const float* __restrict__ b_obs,
                   const float* __restrict__ b_ih,  const float* __restrict__ b_hh,
                   const float* __restrict__ b_val, const float* __restrict__ b_dec,
                   float* __restrict__ out)
{
    extern __shared__ char smem_raw[];
    Smem& s = *reinterpret_cast<Smem*>(smem_raw);

    const int tid  = threadIdx.x;
    const int bid  = blockIdx.x;
    const int wid  = tid >> 5;
    const int lane = tid & 31;
    const int g    = lane >> 2;
    const int t4   = lane & 3;
    const int n0g  = wid * 32;

    float acc[64];

    // ---- P1: load obs [64 x 128] -> a1 hi/lo ----
    {
        const float* ob = obs + (size_t)bid * ROWS * 128;
        for (int idx = tid; idx < ROWS * 128; idx += 256) {
            int r = idx >> 7;
            int k = idx & 127;
            float v = ob[idx];
            __nv_bfloat16 h = __float2bfloat16(v);
            s.a1h[r * LDA_ACT + k] = h;
            s.a1l[r * LDA_ACT + k] = __float2bfloat16(v - __bfloat162float(h));
        }
    }
    __syncthreads();

    // ---- P2: x = relu(obs @ W_enc^T + b_enc) -> a2 ----
    zero64(acc);
    gemm_pass<4, false>(s, s.a1h, s.a1l, g_whi + OFF_ENC, g_wlo + OFF_ENC,
                        0, 128, 128, 256, n0g, g, t4, tid, acc);
    for (int mt = 0; mt < 4; ++mt) {
        for (int nt = 0; nt < 4; ++nt) {
            int col = n0g + nt * 8 + 2 * t4;
            int r0 = mt * 16 + g;
            const float* d = acc + (mt * 4 + nt) * 4;
            float b0 = __ldg(&b_enc[col]);
            float b1 = __ldg(&b_enc[col + 1]);
            store_pair(s.a2h, s.a2l, r0, col, fmaxf(d[0] + b0, 0.0f), fmaxf(d[1] + b1, 0.0f));
            store_pair(s.a2h, s.a2l, r0 + 8, col, fmaxf(d[2] + b0, 0.0f), fmaxf(d[3] + b1, 0.0f));
        }
    }

    // ---- P3: h = x @ W_obs^T + b_obs -> a1 ----
    zero64(acc);
    gemm_pass<4, false>(s, s.a2h, s.a2l, g_whi + OFF_OBS, g_wlo + OFF_OBS,
                        0, 256, 256, 256, n0g, g, t4, tid, acc);
    for (int mt = 0; mt < 4; ++mt) {
        for (int nt = 0; nt < 4; ++nt) {
            int col = n0g + nt * 8 + 2 * t4;
            int r0 = mt * 16 + g;
            const float* d = acc + (mt * 4 + nt) * 4;
            float b0 = __ldg(&b_obs[col]);
            float b1 = __ldg(&b_obs[col + 1]);
            store_pair(s.a1h, s.a1l, r0, col, d[0] + b0, d[1] + b1);
            store_pair(s.a1h, s.a1l, r0 + 8, col, d[2] + b0, d[3] + b1);
        }
    }
    __syncthreads();

    // ---- P4: S = column sums of h ----
    {
        float sum = 0.0f;
#pragma unroll 8
        for (int r = 0; r < ROWS; ++r) {
            sum += __bfloat162float(s.a1h[r * LDA_ACT + tid]) +
                   __bfloat162float(s.a1l[r * LDA_ACT + tid]);
        }
        s.S[tid] = sum;
    }
    __syncthreads();

    // ======== P5 GRU. Gate fragments round-trip through a2 (own-thread). ====

    // r gate
    zero64(acc);
    gemm_pass<4, false>(s, s.a1h, s.a1l, g_whi + OFF_HH, g_wlo + OFF_HH,
                        0, 256, 256, 256, n0g, g, t4, tid, acc);
    s.t[tid] = 0.0f;
    gemm_pass<4, true>(s, s.a1h, s.a1l, g_whi + OFF_IH, g_wlo + OFF_IH,
                       0, 256, 256, 256, n0g, g, t4, tid, acc);
    for (int mt = 0; mt < 4; ++mt) {
        for (int nt = 0; nt < 4; ++nt) {
            int col = n0g + nt * 8 + 2 * t4;
            int r0 = mt * 16 + g;
            float* d = acc + (mt * 4 + nt) * 4;
            float c0 = -s.t[col] + __ldg(&b_ih[col]) + __ldg(&b_hh[col]);
            float c1 = -s.t[col + 1] + __ldg(&b_ih[col + 1]) + __ldg(&b_hh[col + 1]);
            store_pair(s.a2h, s.a2l, r0, col, sigm(d[0] + c0), sigm(d[1] + c1));
            store_pair(s.a2h, s.a2l, r0 + 8, col, sigm(d[2] + c0), sigm(d[3] + c1));
        }
    }

    // n gate: acc = h.Whh_n; acc = r*(acc+b_hh_n); acc += h.Wih'_n; n = tanh(acc - t + b_ih_n)
    zero64(acc);
    gemm_pass<4, false>(s, s.a1h, s.a1l, g_whi + OFF_HH, g_wlo + OFF_HH,
                        512, 256, 256, 256, n0g, g, t4, tid, acc);
    for (int mt = 0; mt < 4; ++mt) {
        for (int nt = 0; nt < 4; ++nt) {
            int col = n0g + nt * 8 + 2 * t4;
            int r0 = mt * 16 + g;
            float* d = acc + (mt * 4 + nt) * 4;
            float b0 = __ldg(&b_hh[512 + col]);
            float b1 = __ldg(&b_hh[512 + col + 1]);
            float2 ra = load_pair(s.a2h, s.a2l, r0, col);
            float2 rb = load_pair(s.a2h, s.a2l, r0 + 8, col);
            d[0] = ra.x * (d[0] + b0);
            d[1] = ra.y * (d[1] + b1);
            d[2] = rb.x * (d[2] + b0);
            d[3] = rb.y * (d[3] + b1);
        }
    }
    s.t[tid] = 0.0f;
    gemm_pass<4, true>(s, s.a1h, s.a1l, g_whi + OFF_IH, g_wlo + OFF_IH,
                       512, 256, 256, 256, n0g, g, t4, tid, acc);
    for (int mt = 0; mt < 4; ++mt) {
        for (int nt = 0; nt < 4; ++nt) {
            int col = n0g + nt * 8 + 2 * t4;
            int r0 = mt * 16 + g;
            float* d = acc + (mt * 4 + nt) * 4;
            float c0 = -s.t[col] + __ldg(&b_ih[512 + col]);
            float c1 = -s.t[col + 1] + __ldg(&b_ih[512 + col + 1]);
            store_pair(s.a2h, s.a2l, r0, col, tanhf(d[0] + c0), tanhf(d[1] + c1));
            store_pair(s.a2h, s.a2l, r0 + 8, col, tanhf(d[2] + c0), tanhf(d[3] + c1));
        }
    }

    // z gate + blend: h_new = (1-z)*n + z*h_old -> a2
    zero64(acc);
    gemm_pass<4, false>(s, s.a1h, s.a1l, g_whi + OFF_HH, g_wlo + OFF_HH,
                        256, 256, 256, 256, n0g, g, t4, tid, acc);
    s.t[tid] = 0.0f;
    gemm_pass<4, true>(s, s.a1h, s.a1l, g_whi + OFF_IH, g_wlo + OFF_IH,
                       256, 256, 256, 256, n0g, g, t4, tid, acc);
    for (int mt = 0; mt < 4; ++mt) {
        for (int nt = 0; nt < 4; ++nt) {
            int col = n0g + nt * 8 + 2 * t4;
            int r0 = mt * 16 + g;
            float* d = acc + (mt * 4 + nt) * 4;
            float c0 = -s.t[col] + __ldg(&b_ih[256 + col]) + __ldg(&b_hh[256 + col]);
            float c1 = -s.t[col + 1] + __ldg(&b_ih[256 + col + 1]) + __ldg(&b_hh[256 + col + 1]);
            float z0 = sigm(d[0] + c0);
            float z1 = sigm(d[1] + c1);
            float z2 = sigm(d[2] + c0);
            float z3 = sigm(d[3] + c1);
            float2 na = load_pair(s.a2h, s.a2l, r0, col);
            float2 nb = load_pair(s.a2h, s.a2l, r0 + 8, col);
            float2 ha = load_pair(s.a1h, s.a1l, r0, col);
            float2 hb = load_pair(s.a1h, s.a1l, r0 + 8, col);
            store_pair(s.a2h, s.a2l, r0, col,
                       (1.0f - z0) * na.x + z0 * ha.x,
                       (1.0f - z1) * na.y + z1 * ha.y);
            store_pair(s.a2h, s.a2l, r0 + 8, col,
                       (1.0f - z2) * nb.x + z2 * hb.x,
                       (1.0f - z3) * nb.y + z3 * hb.y);
        }
    }

    // ---- P6: v = h_new @ W_val^T + b_val -> a1 ----
    zero64(acc);
    gemm_pass<4, false>(s, s.a2h, s.a2l, g_whi + OFF_VAL, g_wlo + OFF_VAL,
                        0, 256, 256, 256, n0g, g, t4, tid, acc);
    for (int mt = 0; mt < 4; ++mt) {
        for (int nt = 0; nt < 4; ++nt) {
            int col = n0g + nt * 8 + 2 * t4;
            int r0 = mt * 16 + g;
            const float* d = acc + (mt * 4 + nt) * 4;
            float b0 = __ldg(&b_val[col]);
            float b1 = __ldg(&b_val[col + 1]);
            store_pair(s.a1h, s.a1l, r0, col, d[0] + b0, d[1] + b1);
            store_pair(s.a1h, s.a1l, r0 + 8, col, d[2] + b0, d[3] + b1);
        }
    }

    // ---- P7: out = v @ W_dec^T + b_dec (64 cols, warp owns 8) ----
    {
        float ad[16];
#pragma unroll
        for (int i = 0; i < 16; ++i) { ad[i] = 0.0f; }
        int n0d = wid * 8;
        gemm_pass<1, false>(s, s.a1h, s.a1l, g_whi + OFF_DEC, g_wlo + OFF_DEC,
                            0, 256, 256, 64, n0d, g, t4, tid, ad);
        float* out_b = out + (size_t)bid * ROWS * 64;
        int col = n0d + 2 * t4;
        float b0 = __ldg(&b_dec[col]);
        float b1 = __ldg(&b_dec[col + 1]);
        for (int mt = 0; mt < 4; ++mt) {
            int r0 = mt * 16 + g;
            const float* d = ad + mt * 4;
            float2 o0 = make_float2(d[0] + b0, d[1] + b1);
            float2 o1 = make_float2(d[2] + b0, d[3] + b1);
            *reinterpret_cast<float2*>(&out_b[r0 * 64 + col]) = o0;
            *reinterpret_cast<float2*>(&out_b[(r0 + 8) * 64 + col]) = o1;
        }
    }
}

extern "C" void kernel_launch(void* const* d_in, const int* in_sizes, int n_in,
                              void* d_out, int out_size)
{
    const float* obs   = (const float*)d_in[0];
    const float* W_enc = (const float*)d_in[1];
    const float* b_enc = (const float*)d_in[2];
    const float* W_obs = (const float*)d_in[3];
    const float* b_obs = (const float*)d_in[4];
    const float* W_ih  = (const float*)d_in[5];
    const float* b_ih  = (const float*)d_in[6];
    const float* W_hh  = (const float*)d_in[7];
    const float* b_hh  = (const float*)d_in[8];
    const float* W_val = (const float*)d_in[9];
    const float* b_val = (const float*)d_in[10];
    const float* W_dec = (const float*)d_in[11];
    const float* b_dec = (const float*)d_in[12];
    float* out = (float*)d_out;
    (void)in_sizes; (void)n_in; (void)out_size;

    conv_weights<<<(W_TOTAL + 255) / 256, 256>>>(W_enc, W_obs, W_ih, W_hh, W_val, W_dec);

    cudaFuncSetAttribute(commnet_mma_kernel,
                         cudaFuncAttributeMaxDynamicSharedMemorySize, (int)sizeof(Smem));
    commnet_mma_kernel<<<256, 256, sizeof(Smem)>>>(
        obs, b_enc, b_obs, b_ih, b_hh, b_val, b_dec, out);
}

// round 11
// speedup vs baseline: 2.2988x; 1.8131x over previous
#include <cuda_runtime.h>
#include <cuda_bf16.h>
#include <stdint.h>
#include <math.h>

// CommNetWork fused, split-bf16 mma.sync (m16n8k16, fp32 acc), 512 threads/CTA.
// B=256, N=64 agents, D_IN=128, H0=256, H1=256, H2=64. One CTA per batch.
// Precision: x*w ~= xh*wh + xh*wl + xl*wh (hi/lo bf16 split, fp32 accumulate).
// Comm factorization: c=(S-h)/64; W_ih pre-scaled by -1/64 so gi and gh share
// one accumulator; S-term t[col] accumulated from staged chunks.
// 16 warps (4/SMSP) to hide HMMA + LDS latency (R7 ran 8 warps: tensor=18%).

#define ROWS    64
#define NTHREADS 512
#define LDA_ACT 264   // bf16 elems per activation row (256+8 pad)
#define LDW     40    // bf16 elems per weight-chunk row (32+8 pad)
#define KCH     32    // k per staged chunk (double buffered)

#define OFF_ENC 0
#define OFF_OBS 32768
#define OFF_IH  98304
#define OFF_HH  294912
#define OFF_VAL 491520
#define OFF_DEC 557056
#define W_TOTAL 573440

__device__ __align__(16) __nv_bfloat16 g_whi[W_TOTAL];
__device__ __align__(16) __nv_bfloat16 g_wlo[W_TOTAL];

struct Smem {
    __nv_bfloat16 a1h[ROWS * LDA_ACT];
    __nv_bfloat16 a1l[ROWS * LDA_ACT];
    __nv_bfloat16 a2h[ROWS * LDA_ACT];
    __nv_bfloat16 a2l[ROWS * LDA_ACT];
    __nv_bfloat16 wh[2][256 * LDW];
    __nv_bfloat16 wl[2][256 * LDW];
    float S[256];
    float t[256];
};  // 219136 bytes

// ------------------------- weight conversion pre-pass -------------------
__global__ void conv_weights(const float* __restrict__ enc, const float* __restrict__ obsw,
                             const float* __restrict__ ih,  const float* __restrict__ hh,
                             const float* __restrict__ val, const float* __restrict__ dec)
{
    int i = blockIdx.x * blockDim.x + threadIdx.x;
    if (i >= W_TOTAL) return;
    const float* src;
    int off;
    float scale = 1.0f;
    if (i < OFF_OBS)      { src = enc;  off = i; }
    else if (i < OFF_IH)  { src = obsw; off = i - OFF_OBS; }
    else if (i < OFF_HH)  { src = ih;   off = i - OFF_IH; scale = -0.015625f; }
    else if (i < OFF_VAL) { src = hh;   off = i - OFF_HH; }
    else if (i < OFF_DEC) { src = val;  off = i - OFF_VAL; }
    else                  { src = dec;  off = i - OFF_DEC; }
    float v = src[off] * scale;
    __nv_bfloat16 h = __float2bfloat16(v);
    g_whi[i] = h;
    g_wlo[i] = __float2bfloat16(v - __bfloat162float(h));
}

// ------------------------- device helpers --------------------------------
__device__ __forceinline__ float sigm(float x) { return 1.0f / (1.0f + __expf(-x)); }

__device__ __forceinline__ void cp16(void* dst, const void* src) {
    uint32_t d = (uint32_t)__cvta_generic_to_shared(dst);
    asm volatile("cp.async.cg.shared.global [%0], [%1], 16;\n" :: "r"(d), "l"(src));
}
__device__ __forceinline__ void cp_commit() { asm volatile("cp.async.commit_group;\n" ::); }
__device__ __forceinline__ void cp_wait1()  { asm volatile("cp.async.wait_group 1;\n" ::); }
__device__ __forceinline__ void cp_wait0()  { asm volatile("cp.async.wait_group 0;\n" ::); }

__device__ __forceinline__ void mma_bf16(float* d,
                                         uint32_t a0, uint32_t a1, uint32_t a2, uint32_t a3,
                                         uint32_t b0, uint32_t b1)
{
    asm volatile("mma.sync.aligned.m16n8k16.row.col.f32.bf16.bf16.f32 "
                 "{%0,%1,%2,%3}, {%4,%5,%6,%7}, {%8,%9}, {%0,%1,%2,%3};\n"
                 : "+f"(d[0]), "+f"(d[1]), "+f"(d[2]), "+f"(d[3])
                 : "r"(a0), "r"(a1), "r"(a2), "r"(a3), "r"(b0), "r"(b1));
}

__device__ __forceinline__ void stage(Smem& s, int buf,
                                      const __nv_bfloat16* __restrict__ ghi,
                                      const __nv_bfloat16* __restrict__ glo,
                                      int col0, int Ksrc, int k0, int nrows, int tid)
{
    int total = nrows * 4;
    for (int idx = tid; idx < total; idx += NTHREADS) {
        int r = idx >> 2;
        int seg = idx & 3;
        size_t so = (size_t)(col0 + r) * Ksrc + k0 + seg * 8;
        cp16(&s.wh[buf][r * LDW + seg * 8], ghi + so);
        cp16(&s.wl[buf][r * LDW + seg * 8], glo + so);
    }
    cp_commit();
}

// one 32-k chunk: acc += Ahi*Whi + Ahi*Wlo + Alo*Whi   (NT n8-tiles per warp)
template<int NT>
__device__ __forceinline__ void mma_chunk(const __nv_bfloat16* __restrict__ ah,
                                          const __nv_bfloat16* __restrict__ al,
                                          const __nv_bfloat16* __restrict__ wh,
                                          const __nv_bfloat16* __restrict__ wl,
                                          int kbase, int n0, int g, int t4, float* acc)
{
#pragma unroll
    for (int ks = 0; ks < 2; ++ks) {
        int klA = kbase + ks * 16 + 2 * t4;
        int klW = ks * 16 + 2 * t4;
        uint32_t bh0[NT], bh1[NT], bl0[NT], bl1[NT];
#pragma unroll
        for (int nt = 0; nt < NT; ++nt) {
            int wrow = (n0 + nt * 8 + g) * LDW + klW;
            bh0[nt] = *(const uint32_t*)&wh[wrow];
            bh1[nt] = *(const uint32_t*)&wh[wrow + 8];
            bl0[nt] = *(const uint32_t*)&wl[wrow];
            bl1[nt] = *(const uint32_t*)&wl[wrow + 8];
        }
#pragma unroll
        for (int mt = 0; mt < 4; ++mt) {
            int ab = (mt * 16 + g) * LDA_ACT + klA;
            uint32_t A0 = *(const uint32_t*)&ah[ab];
            uint32_t A1 = *(const uint32_t*)&ah[ab + 8 * LDA_ACT];
            uint32_t A2 = *(const uint32_t*)&ah[ab + 8];
            uint32_t A3 = *(const uint32_t*)&ah[ab + 8 * LDA_ACT + 8];
            uint32_t L0 = *(const uint32_t*)&al[ab];
            uint32_t L1 = *(const uint32_t*)&al[ab + 8 * LDA_ACT];
            uint32_t L2 = *(const uint32_t*)&al[ab + 8];
            uint32_t L3 = *(const uint32_t*)&al[ab + 8 * LDA_ACT + 8];
#pragma unroll
            for (int nt = 0; nt < NT; ++nt) {
                float* d = acc + (mt * NT + nt) * 4;
                mma_bf16(d, A0, A1, A2, A3, bh0[nt], bh1[nt]);
                mma_bf16(d, A0, A1, A2, A3, bl0[nt], bl1[nt]);
                mma_bf16(d, L0, L1, L2, L3, bh0[nt], bh1[nt]);
            }
        }
    }
}

// NACT: number of warps that run MMAs (all warps stage + sync).
template<int NT, bool TACC, int NACT>
__device__ __forceinline__ void gemm_pass(Smem& s,
                                          const __nv_bfloat16* __restrict__ ah,
                                          const __nv_bfloat16* __restrict__ al,
                                          const __nv_bfloat16* __restrict__ ghi,
                                          const __nv_bfloat16* __restrict__ glo,
                                          int col0, int Ksrc, int Kdim, int nrows,
                                          int n0, int g, int t4, int tid, int wid, float* acc)
{
    const int nch = Kdim / KCH;
    stage(s, 0, ghi, glo, col0, Ksrc, 0, nrows, tid);
    for (int c = 0; c < nch; ++c) {
        int cur = c & 1;
        bool more = (c + 1 < nch);
        if (more) {
            stage(s, 1 - cur, ghi, glo, col0, Ksrc, (c + 1) * KCH, nrows, tid);
            cp_wait1();
        } else {
            cp_wait0();
        }
        __syncthreads();
        if (TACC && tid < 256) {
            float sum = 0.0f;
            const __nv_bfloat16* w1 = &s.wh[cur][tid * LDW];
            const __nv_bfloat16* w2 = &s.wl[cur][tid * LDW];
#pragma unroll
            for (int kk = 0; kk < KCH; ++kk) {
                sum += s.S[c * KCH + kk] *
                       (__bfloat162float(w1[kk]) + __bfloat162float(w2[kk]));
            }
            s.t[tid] += sum;
        }
        if (wid < NACT) {
            mma_chunk<NT>(ah, al, s.wh[cur], s.wl[cur], c * KCH, n0, g, t4, acc);
        }
        __syncthreads();
    }
}

__device__ __forceinline__ void store_pair(__nv_bfloat16* hi, __nv_bfloat16* lo,
                                           int row, int col, float v0, float v1)
{
    __nv_bfloat16 h0 = __float2bfloat16(v0);
    __nv_bfloat16 h1 = __float2bfloat16(v1);
    __nv_bfloat162 hp;
    hp.x = h0;
    hp.y = h1;
    __nv_bfloat162 lp;
    lp.x = __float2bfloat16(v0 - __bfloat162float(h0));
    lp.y = __float2bfloat16(v1 - __bfloat162float(h1));
    *reinterpret_cast<__nv_bfloat162*>(&hi[row * LDA_ACT + col]) = hp;
    *reinterpret_cast<__nv_bfloat162*>(&lo[row * LDA_ACT + col]) = lp;
}

__device__ __forceinline__ float2 load_pair(const __nv_bfloat16* hi, const __nv_bfloat16* lo,
                                            int row, int col)
{
    __nv_bfloat162 hp = *reinterpret_cast<const __nv_bfloat162*>(&hi[row * LDA_ACT + col]);
    __nv_bfloat162 lp = *reinterpret_cast<const __nv_bfloat162*>(&lo[row * LDA_ACT + col]);
    float2 r;
    r.x = __bfloat162float(hp.x) + __bfloat162float(lp.x);
    r.y = __bfloat162float(hp.y) + __bfloat162float(lp.y);
    return r;
}

__device__ __forceinline__ void zero32(float* a)
{
#pragma unroll
    for (int i = 0; i < 32; ++i) { a[i] = 0.0f; }
}

// ------------------------- main fused kernel -----------------------------
__global__ void __launch_bounds__(NTHREADS, 1)
commnet_mma_kernel(const float* __restrict__ obs,
                   const float* __restrict__ b_enc, const float* __restrict__ b_obs,
                   const float* __restrict__ b_ih,  const float* __restrict__ b_hh,
                   const float* __restrict__ b_val, const float* __restrict__ b_dec,
                   float* __restrict__ out)
{
    extern __shared__ char smem_raw[];
    Smem& s = *reinterpret_cast<Smem*>(smem_raw);

    const int tid  = threadIdx.x;
    const int bid  = blockIdx.x;
    const int wid  = tid >> 5;
    const int lane = tid & 31;
    const int g    = lane >> 2;
    const int t4   = lane & 3;
    const int n0g  = wid * 16;   // warp's 16-col base in 256-wide outputs

    float acc[32];

    // ---- P1: load obs [64 x 128] -> a1 hi/lo ----
    {
        const float* ob = obs + (size_t)bid * ROWS * 128;
        for (int idx = tid; idx < ROWS * 128; idx += NTHREADS) {
            int r = idx >> 7;
            int k = idx & 127;
            float v = ob[idx];
            __nv_bfloat16 h = __float2bfloat16(v);
            s.a1h[r * LDA_ACT + k] = h;
            s.a1l[r * LDA_ACT + k] = __float2bfloat16(v - __bfloat162float(h));
        }
    }
    __syncthreads();

    // ---- P2: x = relu(obs @ W_enc^T + b_enc) -> a2 ----
    zero32(acc);
    gemm_pass<2, false, 16>(s, s.a1h, s.a1l, g_whi + OFF_ENC, g_wlo + OFF_ENC,
                            0, 128, 128, 256, n0g, g, t4, tid, wid, acc);
    for (int mt = 0; mt < 4; ++mt) {
        for (int nt = 0; nt < 2; ++nt) {
            int col = n0g + nt * 8 + 2 * t4;
            int r0 = mt * 16 + g;
            const float* d = acc + (mt * 2 + nt) * 4;
            float b0 = __ldg(&b_enc[col]);
            float b1 = __ldg(&b_enc[col + 1]);
            store_pair(s.a2h, s.a2l, r0, col, fmaxf(d[0] + b0, 0.0f), fmaxf(d[1] + b1, 0.0f));
            store_pair(s.a2h, s.a2l, r0 + 8, col, fmaxf(d[2] + b0, 0.0f), fmaxf(d[3] + b1, 0.0f));
        }
    }

    // ---- P3: h = x @ W_obs^T + b_obs -> a1 ----
    zero32(acc);
    gemm_pass<2, false, 16>(s, s.a2h, s.a2l, g_whi + OFF_OBS, g_wlo + OFF_OBS,
                            0, 256, 256, 256, n0g, g, t4, tid, wid, acc);
    for (int mt = 0; mt < 4; ++mt) {
        for (int nt = 0; nt < 2; ++nt) {
            int col = n0g + nt * 8 + 2 * t4;
            int r0 = mt * 16 + g;
            const float* d = acc + (mt * 2 + nt) * 4;
            float b0 = __ldg(&b_obs[col]);
            float b1 = __ldg(&b_obs[col + 1]);
            store_pair(s.a1h, s.a1l, r0, col, d[0] + b0, d[1] + b1);
            store_pair(s.a1h, s.a1l, r0 + 8, col, d[2] + b0, d[3] + b1);
        }
    }
    __syncthreads();

    // ---- P4: S = column sums of h ----
    if (tid < 256) {
        float sum = 0.0f;
#pragma unroll 8
        for (int r = 0; r < ROWS; ++r) {
            sum += __bfloat162float(s.a1h[r * LDA_ACT + tid]) +
                   __bfloat162float(s.a1l[r * LDA_ACT + tid]);
        }
        s.S[tid] = sum;
        s.t[tid] = 0.0f;
    }
    __syncthreads();

    // ======== P5 GRU (r, n, z; fragments round-trip through a2) ========

    // r gate
    zero32(acc);
    gemm_pass<2, false, 16>(s, s.a1h, s.a1l, g_whi + OFF_HH, g_wlo + OFF_HH,
                            0, 256, 256, 256, n0g, g, t4, tid, wid, acc);
    gemm_pass<2, true, 16>(s, s.a1h, s.a1l, g_whi + OFF_IH, g_wlo + OFF_IH,
                           0, 256, 256, 256, n0g, g, t4, tid, wid, acc);
    for (int mt = 0; mt < 4; ++mt) {
        for (int nt = 0; nt < 2; ++nt) {
            int col = n0g + nt * 8 + 2 * t4;
            int r0 = mt * 16 + g;
            float* d = acc + (mt * 2 + nt) * 4;
            float c0 = -s.t[col] + __ldg(&b_ih[col]) + __ldg(&b_hh[col]);
            float c1 = -s.t[col + 1] + __ldg(&b_ih[col + 1]) + __ldg(&b_hh[col + 1]);
            store_pair(s.a2h, s.a2l, r0, col, sigm(d[0] + c0), sigm(d[1] + c1));
            store_pair(s.a2h, s.a2l, r0 + 8, col, sigm(d[2] + c0), sigm(d[3] + c1));
        }
    }
    __syncthreads();
    if (tid < 256) { s.t[tid] = 0.0f; }

    // n gate
    zero32(acc);
    gemm_pass<2, false, 16>(s, s.a1h, s.a1l, g_whi + OFF_HH, g_wlo + OFF_HH,
                            512, 256, 256, 256, n0g, g, t4, tid, wid, acc);
    for (int mt = 0; mt < 4; ++mt) {
        for (int nt = 0; nt < 2; ++nt) {
            int col = n0g + nt * 8 + 2 * t4;
            int r0 = mt * 16 + g;
            float* d = acc + (mt * 2 + nt) * 4;
            float b0 = __ldg(&b_hh[512 + col]);
            float b1 = __ldg(&b_hh[512 + col + 1]);
            float2 ra = load_pair(s.a2h, s.a2l, r0, col);
            float2 rb = load_pair(s.a2h, s.a2l, r0 + 8, col);
            d[0] = ra.x * (d[0] + b0);
            d[1] = ra.y * (d[1] + b1);
            d[2] = rb.x * (d[2] + b0);
            d[3] = rb.y * (d[3] + b1);
        }
    }
    gemm_pass<2, true, 16>(s, s.a1h, s.a1l, g_whi + OFF_IH, g_wlo + OFF_IH,
                           512, 256, 256, 256, n0g, g, t4, tid, wid, acc);
    for (int mt = 0; mt < 4; ++mt) {
        for (int nt = 0; nt < 2; ++nt) {
            int col = n0g + nt * 8 + 2 * t4;
            int r0 = mt * 16 + g;
            float* d = acc + (mt * 2 + nt) * 4;
            float c0 = -s.t[col] + __ldg(&b_ih[512 + col]);
            float c1 = -s.t[col + 1] + __ldg(&b_ih[512 + col + 1]);
            store_pair(s.a2h, s.a2l, r0, col, tanhf(d[0] + c0), tanhf(d[1] + c1));
            store_pair(s.a2h, s.a2l, r0 + 8, col, tanhf(d[2] + c0), tanhf(d[3] + c1));
        }
    }
    __syncthreads();
    if (tid < 256) { s.t[tid] = 0.0f; }

    // z gate + blend
    zero32(acc);
    gemm_pass<2, false, 16>(s, s.a1h, s.a1l, g_whi + OFF_HH, g_wlo + OFF_HH,
                            256, 256, 256, 256, n0g, g, t4, tid, wid, acc);
    gemm_pass<2, true, 16>(s, s.a1h, s.a1l, g_whi + OFF_IH, g_wlo + OFF_IH,
                           256, 256, 256, 256, n0g, g, t4, tid, wid, acc);
    for (int mt = 0; mt < 4; ++mt) {
        for (int nt = 0; nt < 2; ++nt) {
            int col = n0g + nt * 8 + 2 * t4;
            int r0 = mt * 16 + g;
            float* d = acc + (mt * 2 + nt) * 4;
            float c0 = -s.t[col] + __ldg(&b_ih[256 + col]) + __ldg(&b_hh[256 + col]);
            float c1 = -s.t[col + 1] + __ldg(&b_ih[256 + col + 1]) + __ldg(&b_hh[256 + col + 1]);
            float z0 = sigm(d[0] + c0);
            float z1 = sigm(d[1] + c1);
            float z2 = sigm(d[2] + c0);
            float z3 = sigm(d[3] + c1);
            float2 na = load_pair(s.a2h, s.a2l, r0, col);
            float2 nb = load_pair(s.a2h, s.a2l, r0 + 8, col);
            float2 ha = load_pair(s.a1h, s.a1l, r0, col);
            float2 hb = load_pair(s.a1h, s.a1l, r0 + 8, col);
            store_pair(s.a2h, s.a2l, r0, col,
                       (1.0f - z0) * na.x + z0 * ha.x,
                       (1.0f - z1) * na.y + z1 * ha.y);
            store_pair(s.a2h, s.a2l, r0 + 8, col,
                       (1.0f - z2) * nb.x + z2 * hb.x,
                       (1.0f - z3) * nb.y + z3 * hb.y);
        }
    }

    // ---- P6: v = h_new @ W_val^T + b_val -> a1 ----
    zero32(acc);
    gemm_pass<2, false, 16>(s, s.a2h, s.a2l, g_whi + OFF_VAL, g_wlo + OFF_VAL,
                            0, 256, 256, 256, n0g, g, t4, tid, wid, acc);
    for (int mt = 0; mt < 4; ++mt) {
        for (int nt = 0; nt < 2; ++nt) {
            int col = n0g + nt * 8 + 2 * t4;
            int r0 = mt * 16 + g;
            const float* d = acc + (mt * 2 + nt) * 4;
            float b0 = __ldg(&b_val[col]);
            float b1 = __ldg(&b_val[col + 1]);
            store_pair(s.a1h, s.a1l, r0, col, d[0] + b0, d[1] + b1);
            store_pair(s.a1h, s.a1l, r0 + 8, col, d[2] + b0, d[3] + b1);
        }
    }

    // ---- P7: out = v @ W_dec^T + b_dec (64 cols; warps 0..7 own 8 each) ----
    {
        float ad[16];
#pragma unroll
        for (int i = 0; i < 16; ++i) { ad[i] = 0.0f; }
        int n0d = (wid & 7) * 8;
        gemm_pass<1, false, 8>(s, s.a1h, s.a1l, g_whi + OFF_DEC, g_wlo + OFF_DEC,
                               0, 256, 256, 64, n0d, g, t4, tid, wid, ad);
        if (wid < 8) {
            float* out_b = out + (size_t)bid * ROWS * 64;
            int col = n0d + 2 * t4;
            float b0 = __ldg(&b_dec[col]);
            float b1 = __ldg(&b_dec[col + 1]);
            for (int mt = 0; mt < 4; ++mt) {
                int r0 = mt * 16 + g;
                const float* d = ad + mt * 4;
                float2 o0 = make_float2(d[0] + b0, d[1] + b1);
                float2 o1 = make_float2(d[2] + b0, d[3] + b1);
                *reinterpret_cast<float2*>(&out_b[r0 * 64 + col]) = o0;
                *reinterpret_cast<float2*>(&out_b[(r0 + 8) * 64 + col]) = o1;
            }
        }
    }
}

extern "C" void kernel_launch(void* const* d_in, const int* in_sizes, int n_in,
                              void* d_out, int out_size)
{
    const float* obs   = (const float*)d_in[0];
    const float* W_enc = (const float*)d_in[1];
    const float* b_enc = (const float*)d_in[2];
    const float* W_obs = (const float*)d_in[3];
    const float* b_obs = (const float*)d_in[4];
    const float* W_ih  = (const float*)d_in[5];
    const float* b_ih  = (const float*)d_in[6];
    const float* W_hh  = (const float*)d_in[7];
    const float* b_hh  = (const float*)d_in[8];
    const float* W_val = (const float*)d_in[9];
    const float* b_val = (const float*)d_in[10];
    const float* W_dec = (const float*)d_in[11];
    const float* b_dec = (const float*)d_in[12];
    float* out = (float*)d_out;
    (void)in_sizes; (void)n_in; (void)out_size;

    conv_weights<<<(W_TOTAL + 255) / 256, 256>>>(W_enc, W_obs, W_ih, W_hh, W_val, W_dec);

    cudaFuncSetAttribute(commnet_mma_kernel,
                         cudaFuncAttributeMaxDynamicSharedMemorySize, (int)sizeof(Smem));
    commnet_mma_kernel<<<256, NTHREADS, sizeof(Smem)>>>(
        obs, b_enc, b_obs, b_ih, b_hh, b_val, b_dec, out);
}